// round 1
// baseline (speedup 1.0000x reference)
#include <cuda_runtime.h>
#include <cuda_bf16.h>

// Problem: BiaffineAttention  B=16, S=512, H=1024, A=500
//   head = ReLU(X @ w1h^T + b1h) @ w2h^T + b2h          [8192, 500]
//   dep  = ReLU(X @ w1d^T + b1d) @ w2d^T + b2d          [8192, 500]
//   depW = dep @ Wb^T                                    [8192, 500]
//   scores[b,i,j] = head[b,i,:] . depW[b,j,:] + bb       [16, 512, 512]
//
// All GEMMs are NT (B operand stored [N,K] row-major), handled by one kernel.

#define BM 64
#define BN 64
#define BK 16
#define TM 4
#define TN 4

// 4 scratch buffers of 8192 x 512 fp32 (ld = 512, only cols [0,500) used)
#define LDS_ 512
#define ROWS_ 8192
__device__ float g_scratch[4LL * ROWS_ * LDS_];

__global__ __launch_bounds__(256) void gemm_nt(
    const float* __restrict__ A, int lda, long long sA,
    const float* __restrict__ B, int ldb, long long sB,
    float* __restrict__ C, int ldc, long long sC,
    int M, int N, int K,
    const float* __restrict__ bias, int biasMode, int doRelu)
{
    __shared__ float As[BK][BM];
    __shared__ float Bs[BK][BN];

    const float* Ab = A + (long long)blockIdx.z * sA;
    const float* Bb = B + (long long)blockIdx.z * sB;
    float*       Cb = C + (long long)blockIdx.z * sC;

    const int row0 = blockIdx.y * BM;
    const int col0 = blockIdx.x * BN;
    const int tid  = threadIdx.x;

    // compute mapping: 16x16 threads, each owns a 4x4 microtile
    const int tm = tid >> 4;       // 0..15
    const int tn = tid & 15;       // 0..15

    // load mapping: each thread loads 4 contiguous-k elements of A and of B
    const int lr = tid >> 2;         // 0..63 (row within tile)
    const int lc = (tid & 3) * 4;    // 0,4,8,12 (k within tile)

    float acc[TM][TN];
#pragma unroll
    for (int i = 0; i < TM; i++)
#pragma unroll
        for (int j = 0; j < TN; j++) acc[i][j] = 0.0f;

    for (int k0 = 0; k0 < K; k0 += BK) {
        // ---- fill A tile: As[k][m] ----
        {
            const int r = row0 + lr;
            const bool rok = (r < M);
            const long long base = (long long)r * lda + k0 + lc;
#pragma unroll
            for (int u = 0; u < 4; u++) {
                const int k = k0 + lc + u;
                As[lc + u][lr] = (rok && k < K) ? Ab[base + u] : 0.0f;
            }
        }
        // ---- fill B tile: Bs[k][n] ----
        {
            const int c = col0 + lr;
            const bool cok = (c < N);
            const long long base = (long long)c * ldb + k0 + lc;
#pragma unroll
            for (int u = 0; u < 4; u++) {
                const int k = k0 + lc + u;
                Bs[lc + u][lr] = (cok && k < K) ? Bb[base + u] : 0.0f;
            }
        }
        __syncthreads();

#pragma unroll
        for (int kk = 0; kk < BK; kk++) {
            float a[TM], b[TN];
#pragma unroll
            for (int i = 0; i < TM; i++) a[i] = As[kk][tm * TM + i];
#pragma unroll
            for (int j = 0; j < TN; j++) b[j] = Bs[kk][tn * TN + j];
#pragma unroll
            for (int i = 0; i < TM; i++)
#pragma unroll
                for (int j = 0; j < TN; j++)
                    acc[i][j] = fmaf(a[i], b[j], acc[i][j]);
        }
        __syncthreads();
    }

    // ---- epilogue ----
#pragma unroll
    for (int i = 0; i < TM; i++) {
        const int r = row0 + tm * TM + i;
        if (r >= M) continue;
#pragma unroll
        for (int j = 0; j < TN; j++) {
            const int c = col0 + tn * TN + j;
            if (c >= N) continue;
            float v = acc[i][j];
            if (biasMode == 1)      v += bias[c];
            else if (biasMode == 2) v += bias[0];
            if (doRelu)             v = fmaxf(v, 0.0f);
            Cb[(long long)r * ldc + c] = v;
        }
    }
}

extern "C" void kernel_launch(void* const* d_in, const int* in_sizes, int n_in,
                              void* d_out, int out_size)
{
    const float* X   = (const float*)d_in[0];   // [16,512,1024] -> [8192,1024]
    const float* w1h = (const float*)d_in[1];   // [500,1024]
    const float* b1h = (const float*)d_in[2];   // [500]
    const float* w2h = (const float*)d_in[3];   // [500,500]
    const float* b2h = (const float*)d_in[4];   // [500]
    const float* w1d = (const float*)d_in[5];   // [500,1024]
    const float* b1d = (const float*)d_in[6];   // [500]
    const float* w2d = (const float*)d_in[7];   // [500,500]
    const float* b2d = (const float*)d_in[8];   // [500]
    const float* Wb  = (const float*)d_in[9];   // [500,500]
    const float* bb  = (const float*)d_in[10];  // [1]
    float* out = (float*)d_out;                 // [16,512,512]

    float* scratch = nullptr;
    cudaGetSymbolAddress((void**)&scratch, g_scratch);
    float* Th   = scratch + 0LL * ROWS_ * LDS_;
    float* Td   = scratch + 1LL * ROWS_ * LDS_;
    float* head = scratch + 2LL * ROWS_ * LDS_;
    float* dep  = scratch + 3LL * ROWS_ * LDS_;
    float* depW = Th;   // Th is dead after stage2-head

    const int M = ROWS_;        // 8192
    const int A_ = 500;
    const int H_ = 1024;

    dim3 blk(256);
    dim3 g1((A_ + BN - 1) / BN, (M + BM - 1) / BM, 1);   // (8, 128)

    // stage 1: Th = ReLU(X @ w1h^T + b1h), Td = ReLU(X @ w1d^T + b1d)
    gemm_nt<<<g1, blk>>>(X, H_, 0, w1h, H_, 0, Th, LDS_, 0, M, A_, H_, b1h, 1, 1);
    gemm_nt<<<g1, blk>>>(X, H_, 0, w1d, H_, 0, Td, LDS_, 0, M, A_, H_, b1d, 1, 1);

    // stage 2: head = Th @ w2h^T + b2h ; dep = Td @ w2d^T + b2d
    gemm_nt<<<g1, blk>>>(Th, LDS_, 0, w2h, A_, 0, head, LDS_, 0, M, A_, A_, b2h, 1, 0);
    gemm_nt<<<g1, blk>>>(Td, LDS_, 0, w2d, A_, 0, dep,  LDS_, 0, M, A_, A_, b2d, 1, 0);

    // bilinear fold: depW = dep @ Wb^T   (Th buffer reused)
    gemm_nt<<<g1, blk>>>(dep, LDS_, 0, Wb, A_, 0, depW, LDS_, 0, M, A_, A_, nullptr, 0, 0);

    // final batched: scores[b] = head[b] @ depW[b]^T + bb   (M=N=512, K=500)
    dim3 gf((512 + BN - 1) / BN, (512 + BM - 1) / BM, 16);  // (8, 8, 16)
    const long long sAB = 512LL * LDS_;      // 512 rows per batch, ld 512
    const long long sC  = 512LL * 512LL;
    gemm_nt<<<gf, blk>>>(head, LDS_, sAB, depW, LDS_, sAB, out, 512, sC,
                         512, 512, A_, bb, 2, 0);
}

// round 2
// speedup vs baseline: 1.7570x; 1.7570x over previous
#include <cuda_runtime.h>
#include <cuda_bf16.h>

// BiaffineAttention  B=16, S=512, H=1024, A=500 (padded to 512 everywhere)
//   Th   = ReLU(X @ w1h_p^T + b1h)        [8192,512]  (cols 500.. = 0)
//   Td   = ReLU(X @ w1d_p^T + b1d)        [8192,512]
//   head = Th @ w2h_p^T + b2h             [8192,512]
//   dep  = Td @ w2d_p^T + b2d             [8192,512]
//   depW = dep @ Wb_p^T                   [8192,512]
//   out[b,i,j] = head[b,i,:512] . depW[b,j,:512] + bb   [16,512,512]
// Zero-padded weights guarantee intermediate padding cols are exactly 0,
// so all GEMMs run guard-free with M%128==0, N==512, K%8==0.

#define BM 128
#define BN 128
#define BK 8

#define ROWS_ 8192
#define LDP_  512

// scratch: 4 intermediates + padded weights
#define OFF_TH   (0LL)
#define OFF_TD   (OFF_TH  + (long long)ROWS_ * LDP_)
#define OFF_HEAD (OFF_TD  + (long long)ROWS_ * LDP_)
#define OFF_DEP  (OFF_HEAD+ (long long)ROWS_ * LDP_)
#define OFF_W1H  (OFF_DEP + (long long)ROWS_ * LDP_)
#define OFF_W1D  (OFF_W1H + 512LL * 1024)
#define OFF_W2H  (OFF_W1D + 512LL * 1024)
#define OFF_W2D  (OFF_W2H + 512LL * 512)
#define OFF_WB   (OFF_W2D + 512LL * 512)
#define SCRATCH_TOTAL (OFF_WB + 512LL * 512)

__device__ float g_scratch[SCRATCH_TOTAL];

// zero-padded copy: src [R,C] row-major -> dst [Rp,Cp] row-major
__global__ void pad_copy(const float* __restrict__ src, float* __restrict__ dst,
                         int R, int C, int Rp, int Cp)
{
    int idx = blockIdx.x * blockDim.x + threadIdx.x;
    int total = Rp * Cp;
    if (idx >= total) return;
    int r = idx / Cp;
    int c = idx - r * Cp;
    dst[idx] = (r < R && c < C) ? src[r * C + c] : 0.0f;
}

// NT GEMM: C[M,N] = A[M,K] @ B[N,K]^T (+bias)(+relu)
// requires: M % 128 == 0, N % 128 == 0, K % 8 == 0, all ld's % 4 == 0,
// pointers 16B aligned.
__global__ __launch_bounds__(256) void gemm128(
    const float* __restrict__ A, int lda, long long sA,
    const float* __restrict__ B, int ldb, long long sB,
    float* __restrict__ C, int ldc, long long sC,
    int K,
    const float* __restrict__ bias, int biasMode, int Nbias, int doRelu)
{
    __shared__ float As[2][BK][BM];
    __shared__ float Bs[2][BK][BN];

    const float* Ab = A + (long long)blockIdx.z * sA;
    const float* Bb = B + (long long)blockIdx.z * sB;
    float*       Cb = C + (long long)blockIdx.z * sC;

    const int tid  = threadIdx.x;
    const int row0 = blockIdx.y * BM;
    const int col0 = blockIdx.x * BN;

    // ---- load mapping: each thread brings one float4 of A and one of B ----
    const int lr = tid >> 1;          // 0..127 : m (for A) / n (for B)
    const int lk = (tid & 1) * 4;     // 0 or 4 : k offset within tile

    const float* aPtr = Ab + (long long)(row0 + lr) * lda + lk;
    const float* bPtr = Bb + (long long)(col0 + lr) * ldb + lk;

    // ---- compute mapping: 16x16 threads, each owns 8x8 ----
    const int tx = tid & 15;          // n group
    const int ty = tid >> 4;          // m group
    const int mB = ty * 8;
    const int nB = tx * 8;

    float acc[8][8];
#pragma unroll
    for (int i = 0; i < 8; i++)
#pragma unroll
        for (int j = 0; j < 8; j++) acc[i][j] = 0.0f;

    const int ntiles = K / BK;

    // prologue: tile 0 -> smem buf 0
    float4 aReg = *(const float4*)aPtr;
    float4 bReg = *(const float4*)bPtr;
    As[0][lk + 0][lr] = aReg.x; As[0][lk + 1][lr] = aReg.y;
    As[0][lk + 2][lr] = aReg.z; As[0][lk + 3][lr] = aReg.w;
    Bs[0][lk + 0][lr] = bReg.x; Bs[0][lk + 1][lr] = bReg.y;
    Bs[0][lk + 2][lr] = bReg.z; Bs[0][lk + 3][lr] = bReg.w;
    __syncthreads();

    for (int t = 0; t < ntiles; ++t) {
        const int buf = t & 1;

        if (t + 1 < ntiles) {
            aReg = *(const float4*)(aPtr + (t + 1) * BK);
            bReg = *(const float4*)(bPtr + (t + 1) * BK);
        }

#pragma unroll
        for (int kk = 0; kk < BK; ++kk) {
            float4 a0 = *(const float4*)&As[buf][kk][mB];
            float4 a1 = *(const float4*)&As[buf][kk][mB + 4];
            float4 b0 = *(const float4*)&Bs[buf][kk][nB];
            float4 b1 = *(const float4*)&Bs[buf][kk][nB + 4];
            float a[8] = {a0.x, a0.y, a0.z, a0.w, a1.x, a1.y, a1.z, a1.w};
            float b[8] = {b0.x, b0.y, b0.z, b0.w, b1.x, b1.y, b1.z, b1.w};
#pragma unroll
            for (int i = 0; i < 8; i++)
#pragma unroll
                for (int j = 0; j < 8; j++)
                    acc[i][j] = fmaf(a[i], b[j], acc[i][j]);
        }

        if (t + 1 < ntiles) {
            const int nb = buf ^ 1;
            As[nb][lk + 0][lr] = aReg.x; As[nb][lk + 1][lr] = aReg.y;
            As[nb][lk + 2][lr] = aReg.z; As[nb][lk + 3][lr] = aReg.w;
            Bs[nb][lk + 0][lr] = bReg.x; Bs[nb][lk + 1][lr] = bReg.y;
            Bs[nb][lk + 2][lr] = bReg.z; Bs[nb][lk + 3][lr] = bReg.w;
            __syncthreads();
        }
    }

    // ---- epilogue ----
    float bv[8];
#pragma unroll
    for (int j = 0; j < 8; j++) {
        const int c = col0 + nB + j;
        bv[j] = 0.0f;
        if (biasMode == 1 && c < Nbias) bv[j] = bias[c];
        else if (biasMode == 2)         bv[j] = bias[0];
    }

#pragma unroll
    for (int i = 0; i < 8; i++) {
        const long long r = row0 + mB + i;
        float v[8];
#pragma unroll
        for (int j = 0; j < 8; j++) {
            float x = acc[i][j] + bv[j];
            v[j] = doRelu ? fmaxf(x, 0.0f) : x;
        }
        float4 v0 = make_float4(v[0], v[1], v[2], v[3]);
        float4 v1 = make_float4(v[4], v[5], v[6], v[7]);
        *(float4*)&Cb[r * ldc + col0 + nB]     = v0;
        *(float4*)&Cb[r * ldc + col0 + nB + 4] = v1;
    }
}

extern "C" void kernel_launch(void* const* d_in, const int* in_sizes, int n_in,
                              void* d_out, int out_size)
{
    const float* X   = (const float*)d_in[0];   // [8192,1024]
    const float* w1h = (const float*)d_in[1];   // [500,1024]
    const float* b1h = (const float*)d_in[2];
    const float* w2h = (const float*)d_in[3];   // [500,500]
    const float* b2h = (const float*)d_in[4];
    const float* w1d = (const float*)d_in[5];
    const float* b1d = (const float*)d_in[6];
    const float* w2d = (const float*)d_in[7];
    const float* b2d = (const float*)d_in[8];
    const float* Wb  = (const float*)d_in[9];
    const float* bb  = (const float*)d_in[10];
    float* out = (float*)d_out;                 // [16,512,512]

    float* s = nullptr;
    cudaGetSymbolAddress((void**)&s, g_scratch);
    float* Th    = s + OFF_TH;
    float* Td    = s + OFF_TD;
    float* head  = s + OFF_HEAD;
    float* dep   = s + OFF_DEP;
    float* w1h_p = s + OFF_W1H;
    float* w1d_p = s + OFF_W1D;
    float* w2h_p = s + OFF_W2H;
    float* w2d_p = s + OFF_W2D;
    float* Wb_p  = s + OFF_WB;
    float* depW  = Th;  // Th dead after head is produced

    // ---- pad weights into zero-padded scratch ----
    {
        int t1 = 512 * 1024, t2 = 512 * 512;
        pad_copy<<<(t1 + 255) / 256, 256>>>(w1h, w1h_p, 500, 1024, 512, 1024);
        pad_copy<<<(t1 + 255) / 256, 256>>>(w1d, w1d_p, 500, 1024, 512, 1024);
        pad_copy<<<(t2 + 255) / 256, 256>>>(w2h, w2h_p, 500, 500, 512, 512);
        pad_copy<<<(t2 + 255) / 256, 256>>>(w2d, w2d_p, 500, 500, 512, 512);
        pad_copy<<<(t2 + 255) / 256, 256>>>(Wb,  Wb_p,  500, 500, 512, 512);
    }

    dim3 blk(256);
    dim3 g1(512 / BN, ROWS_ / BM, 1);   // (4, 64)

    // stage 1: K=1024
    gemm128<<<g1, blk>>>(X, 1024, 0, w1h_p, 1024, 0, Th, LDP_, 0, 1024, b1h, 1, 500, 1);
    gemm128<<<g1, blk>>>(X, 1024, 0, w1d_p, 1024, 0, Td, LDP_, 0, 1024, b1d, 1, 500, 1);

    // stage 2: K=512 (Th/Td cols 500.. are exactly 0)
    gemm128<<<g1, blk>>>(Th, LDP_, 0, w2h_p, 512, 0, head, LDP_, 0, 512, b2h, 1, 500, 0);
    gemm128<<<g1, blk>>>(Td, LDP_, 0, w2d_p, 512, 0, dep,  LDP_, 0, 512, b2d, 1, 500, 0);

    // bilinear fold: depW = dep @ Wb^T
    gemm128<<<g1, blk>>>(dep, LDP_, 0, Wb_p, 512, 0, depW, LDP_, 0, 512, nullptr, 0, 0, 0);

    // final batched: out[b] = head[b] @ depW[b]^T + bb  (K=512, padding exact 0)
    dim3 gf(512 / BN, 512 / BM, 16);    // (4, 4, 16)
    const long long sAB = 512LL * LDP_;
    const long long sC  = 512LL * 512LL;
    gemm128<<<gf, blk>>>(head, LDP_, sAB, depW, LDP_, sAB, out, 512, sC,
                         512, bb, 2, 0, 0);
}